// round 16
// baseline (speedup 1.0000x reference)
#include <cuda_runtime.h>
#include <cuda_bf16.h>
#include <cmath>
#include <cstdint>

#define TT    2048
#define HIDD  4096
#define NHQ   32
#define NHKV  8
#define DHD   128
#define GSZ   32
#define SM_SCALE 0.088388347648318447f   // 1/sqrt(128)
#define KMARG 1.5e-3f
#define VMARG 1.5e-3f

// ---------------- device scratch (no runtime allocation allowed) ----------
__device__ float g_Q[TT * NHQ * DHD];
__device__ float g_K[TT * NHKV * DHD];
__device__ float g_V[TT * NHKV * DHD];
__device__ float g_rel[NHKV * TT];
__device__ float g_invf[64];

// bf16 split copies
__device__ __nv_bfloat16 g_hs_hi[TT * HIDD],  g_hs_lo[TT * HIDD];
__device__ __align__(16) __nv_bfloat16 g_cx_hi[TT * HIDD],  g_cx_lo[TT * HIDD];
__device__ __nv_bfloat16 g_Wq_hi[HIDD * HIDD], g_Wq_lo[HIDD * HIDD];
__device__ __nv_bfloat16 g_Wo_hi[HIDD * HIDD], g_Wo_lo[HIDD * HIDD];
__device__ __nv_bfloat16 g_Wk_hi[NHKV * DHD * HIDD], g_Wk_lo[NHKV * DHD * HIDD];
__device__ __nv_bfloat16 g_Wv_hi[NHKV * DHD * HIDD], g_Wv_lo[NHKV * DHD * HIDD];
__device__ __align__(16) __nv_bfloat16 g_k_hi[TT * NHKV * DHD], g_k_lo[TT * NHKV * DHD];
__device__ __align__(16) __nv_bfloat16 g_v_hi[TT * NHKV * DHD], g_v_lo[TT * NHKV * DHD];

// GEMM epilogue modes
#define MODE_PLAIN 0
#define MODE_V     1
#define MODE_K     2
#define MODE_Q     3

// ======================= PTX helpers (plain sm_80+ ops only) ===============
__device__ __forceinline__ uint32_t smem_u32(const void* p) {
    uint32_t a;
    asm("{ .reg .u64 t; cvta.to.shared.u64 t, %1; cvt.u32.u64 %0, t; }" : "=r"(a) : "l"(p));
    return a;
}
#define CP_ASYNC16(dst, src) \
    asm volatile("cp.async.cg.shared.global [%0], [%1], 16;" :: "r"(dst), "l"(src) : "memory")
#define CP_COMMIT() asm volatile("cp.async.commit_group;" ::: "memory")
#define CP_WAIT1()  asm volatile("cp.async.wait_group 1;" ::: "memory")
#define CP_WAIT0()  asm volatile("cp.async.wait_group 0;" ::: "memory")

__device__ __forceinline__ void ldmx4(uint32_t addr, uint32_t* r) {
    asm volatile("ldmatrix.sync.aligned.m8n8.x4.shared.b16 {%0,%1,%2,%3}, [%4];"
                 : "=r"(r[0]), "=r"(r[1]), "=r"(r[2]), "=r"(r[3]) : "r"(addr));
}
__device__ __forceinline__ void ldmx4t(uint32_t addr, uint32_t* r) {
    asm volatile("ldmatrix.sync.aligned.m8n8.x4.trans.shared.b16 {%0,%1,%2,%3}, [%4];"
                 : "=r"(r[0]), "=r"(r[1]), "=r"(r[2]), "=r"(r[3]) : "r"(addr));
}
__device__ __forceinline__ void mma16816(float* d, const uint32_t* a,
                                         uint32_t b0, uint32_t b1) {
    asm volatile(
        "mma.sync.aligned.m16n8k16.row.col.f32.bf16.bf16.f32 "
        "{%0,%1,%2,%3}, {%4,%5,%6,%7}, {%8,%9}, {%0,%1,%2,%3};"
        : "+f"(d[0]), "+f"(d[1]), "+f"(d[2]), "+f"(d[3])
        : "r"(a[0]), "r"(a[1]), "r"(a[2]), "r"(a[3]), "r"(b0), "r"(b1));
}

__device__ __forceinline__ void packhl(float x, float y, uint32_t& hi, uint32_t& lo) {
    __nv_bfloat16 hx = __float2bfloat16(x), hy = __float2bfloat16(y);
    __nv_bfloat162 h2(hx, hy);
    hi = *(uint32_t*)&h2;
    __nv_bfloat162 l2(__float2bfloat16(x - __bfloat162float(hx)),
                      __float2bfloat16(y - __bfloat162float(hy)));
    lo = *(uint32_t*)&l2;
}

// warp-cooperative exact fp32 dot of two 4096-vectors
__device__ __forceinline__ float coop_dot(const float* __restrict__ a,
                                          const float* __restrict__ b, int lane) {
    float s = 0.f;
    for (int kk = lane * 4; kk < HIDD; kk += 128) {
        float4 av = *(const float4*)(a + kk);
        float4 bv = *(const float4*)(b + kk);
        s = fmaf(av.x, bv.x, s);
        s = fmaf(av.y, bv.y, s);
        s = fmaf(av.z, bv.z, s);
        s = fmaf(av.w, bv.w, s);
    }
#pragma unroll
    for (int off = 16; off; off >>= 1)
        s += __shfl_xor_sync(0xffffffffu, s, off);
    return s;
}

// ------------- fused split + invfreq init + rel zero -----------------------
#define SPL_C0 2097152     // hs  (TT*HIDD/4)
#define SPL_C1 6291456     // +Wq (HIDD*HIDD/4)
#define SPL_C2 10485760    // +Wo
#define SPL_C3 11534336    // +Wk (NHKV*DHD*HIDD/4)
#define SPL_C4 12582912    // +Wv
#define SPL_HALF (SPL_C4 / 2)

__device__ __forceinline__ void split_one(const float* hs, const float* Wq,
                                          const float* Wo, const float* Wk,
                                          const float* Wv, int i) {
    const float* src;
    __nv_bfloat16 *hi, *lo;
    int off;
    if (i < SPL_C0)      { src = hs; hi = g_hs_hi; lo = g_hs_lo; off = i; }
    else if (i < SPL_C1) { src = Wq; hi = g_Wq_hi; lo = g_Wq_lo; off = i - SPL_C0; }
    else if (i < SPL_C2) { src = Wo; hi = g_Wo_hi; lo = g_Wo_lo; off = i - SPL_C1; }
    else if (i < SPL_C3) { src = Wk; hi = g_Wk_hi; lo = g_Wk_lo; off = i - SPL_C2; }
    else                 { src = Wv; hi = g_Wv_hi; lo = g_Wv_lo; off = i - SPL_C3; }
    float4 v = ((const float4*)src)[off];
    uint32_t h0, h1, l0, l1;
    packhl(v.x, v.y, h0, l0);
    packhl(v.z, v.w, h1, l1);
    ((uint32_t*)hi)[off * 2]     = h0;
    ((uint32_t*)hi)[off * 2 + 1] = h1;
    ((uint32_t*)lo)[off * 2]     = l0;
    ((uint32_t*)lo)[off * 2 + 1] = l1;
}

__global__ __launch_bounds__(256)
void split_all_kernel(const float* __restrict__ hs, const float* __restrict__ Wq,
                      const float* __restrict__ Wo, const float* __restrict__ Wk,
                      const float* __restrict__ Wv) {
    if (blockIdx.x == 0 && threadIdx.x < 64)
        g_invf[threadIdx.x] = (float)(1.0 / pow(10000.0, (double)threadIdx.x / 64.0));
    if (blockIdx.x < 64)
        g_rel[blockIdx.x * 256 + threadIdx.x] = 0.f;
    int i = blockIdx.x * 256 + threadIdx.x;
    split_one(hs, Wq, Wo, Wk, Wv, i);
    split_one(hs, Wq, Wo, Wk, Wv, i + SPL_HALF);
}

// ============ bf16x3 HMMA GEMM body with fused RoPE/split epilogue =========
#define GBK     64
#define GTILEB  (128 * 128)
#define GSTAGEB (4 * GTILEB)
#define GEMM_SMEM (3 * GSTAGEB)          // 192 KB dynamic

__device__ __forceinline__ void load_tile(uint32_t st, const __nv_bfloat16* g,
                                          int row0, int k0, int pitch,
                                          int ch, int rl) {
    const char* gp = (const char*)(g + (size_t)(row0 + rl) * pitch + k0 + ch * 8);
    const size_t gstep = (size_t)32 * pitch * sizeof(__nv_bfloat16);
#pragma unroll
    for (int i = 0; i < 4; i++) {
        int row = rl + i * 32;
        uint32_t sp = st + row * 128 + ((ch ^ (row & 7)) << 4);
        CP_ASYNC16(sp, gp);
        gp += gstep;
    }
}

__device__ void gemm_body(const __nv_bfloat16* __restrict__ Ahi, const __nv_bfloat16* __restrict__ Alo,
                          const __nv_bfloat16* __restrict__ Bhi, const __nv_bfloat16* __restrict__ Blo,
                          float* __restrict__ C, int N, int K, int bx, int by,
                          char* smraw, int mode) {
    const uint32_t sb = smem_u32(smraw);
    const int tid = threadIdx.x, lane = tid & 31, wid = tid >> 5;
    const int wm = wid & 3, wn = wid >> 2;
    const int m0 = by * 128, n0 = bx * 128;
    const int ch = tid & 7, rl = tid >> 3;

    float acc[2][8][4];
#pragma unroll
    for (int a = 0; a < 2; a++)
#pragma unroll
        for (int b = 0; b < 8; b++)
#pragma unroll
            for (int c = 0; c < 4; c++) acc[a][b][c] = 0.f;

    const int lm      = lane >> 3;
    const int lrow    = (lm & 1) * 8 + (lane & 7);
    const int lkchunk = lm >> 1;

    int arb[2], ar7[2], brb[4], br7[4];
#pragma unroll
    for (int mf = 0; mf < 2; mf++) {
        int r = wm * 32 + mf * 16 + lrow;
        arb[mf] = r * 128; ar7[mf] = r & 7;
    }
#pragma unroll
    for (int ng = 0; ng < 4; ng++) {
        int r = wn * 64 + ng * 16 + lrow;
        brb[ng] = r * 128; br7[ng] = r & 7;
    }

    const int nch = K / GBK;
    load_tile(sb,               Ahi, m0, 0, K, ch, rl);
    load_tile(sb +     GTILEB,  Alo, m0, 0, K, ch, rl);
    load_tile(sb + 2 * GTILEB,  Bhi, n0, 0, K, ch, rl);
    load_tile(sb + 3 * GTILEB,  Blo, n0, 0, K, ch, rl);
    CP_COMMIT();
    load_tile(sb + GSTAGEB,              Ahi, m0, GBK, K, ch, rl);
    load_tile(sb + GSTAGEB +     GTILEB, Alo, m0, GBK, K, ch, rl);
    load_tile(sb + GSTAGEB + 2 * GTILEB, Bhi, n0, GBK, K, ch, rl);
    load_tile(sb + GSTAGEB + 3 * GTILEB, Blo, n0, GBK, K, ch, rl);
    CP_COMMIT();

    for (int it = 0; it < nch; it++) {
        CP_WAIT1();
        __syncthreads();

        const uint32_t st  = sb + (it % 3) * GSTAGEB;
        const uint32_t tAh = st,              tAl = st + GTILEB;
        const uint32_t tBh = st + 2 * GTILEB, tBl = st + 3 * GTILEB;

#pragma unroll
        for (int kk = 0; kk < 4; kk++) {
            const int kc = kk * 2 + lkchunk;
            uint32_t ahi[2][4], alo[2][4];
#pragma unroll
            for (int mf = 0; mf < 2; mf++) {
                uint32_t off = arb[mf] + ((kc ^ ar7[mf]) << 4);
                ldmx4(tAh + off, ahi[mf]);
                ldmx4(tAl + off, alo[mf]);
            }
#pragma unroll
            for (int ng = 0; ng < 4; ng++) {
                uint32_t off = brb[ng] + ((kc ^ br7[ng]) << 4);
                uint32_t bh[4], bl[4];
                ldmx4(tBh + off, bh);
                ldmx4(tBl + off, bl);
#pragma unroll
                for (int mf = 0; mf < 2; mf++) {
                    mma16816(acc[mf][ng * 2],     ahi[mf], bh[0], bh[2]);
                    mma16816(acc[mf][ng * 2 + 1], ahi[mf], bh[1], bh[3]);
                    mma16816(acc[mf][ng * 2],     ahi[mf], bl[0], bl[2]);
                    mma16816(acc[mf][ng * 2 + 1], ahi[mf], bl[1], bl[3]);
                    mma16816(acc[mf][ng * 2],     alo[mf], bh[0], bh[2]);
                    mma16816(acc[mf][ng * 2 + 1], alo[mf], bh[1], bh[3]);
                }
            }
        }
        __syncthreads();

        const int cn = it + 2;
        if (cn < nch) {
            const uint32_t sn = sb + (cn % 3) * GSTAGEB;
            load_tile(sn,              Ahi, m0, cn * GBK, K, ch, rl);
            load_tile(sn +     GTILEB, Alo, m0, cn * GBK, K, ch, rl);
            load_tile(sn + 2 * GTILEB, Bhi, n0, cn * GBK, K, ch, rl);
            load_tile(sn + 3 * GTILEB, Blo, n0, cn * GBK, K, ch, rl);
        }
        CP_COMMIT();
    }

    if (mode == MODE_PLAIN) {
        const int er = m0 + wm * 32 + (lane >> 2);
        const int ec = n0 + wn * 64 + (lane & 3) * 2;
#pragma unroll
        for (int mf = 0; mf < 2; mf++)
#pragma unroll
            for (int nf = 0; nf < 8; nf++) {
                float* p0 = C + (size_t)(er + mf * 16) * N + ec + nf * 8;
                float* p1 = C + (size_t)(er + mf * 16 + 8) * N + ec + nf * 8;
                *(float2*)p0 = make_float2(acc[mf][nf][0], acc[mf][nf][1]);
                *(float2*)p1 = make_float2(acc[mf][nf][2], acc[mf][nf][3]);
            }
        return;
    }

    // ---- fused epilogue: stage tile to smem, RoPE pair-exchange, split ----
    CP_WAIT0();
    __syncthreads();
    float* tile = (float*)smraw;
    const int erl = wm * 32 + (lane >> 2);
    const int ecl = wn * 64 + (lane & 3) * 2;
#pragma unroll
    for (int mf = 0; mf < 2; mf++)
#pragma unroll
        for (int nf = 0; nf < 8; nf++) {
            int rr = erl + mf * 16, cc = ecl + nf * 8;
            tile[rr * 128 + cc]           = acc[mf][nf][0];
            tile[rr * 128 + cc + 1]       = acc[mf][nf][1];
            tile[(rr + 8) * 128 + cc]     = acc[mf][nf][2];
            tile[(rr + 8) * 128 + cc + 1] = acc[mf][nf][3];
        }
    __syncthreads();

    const int r  = tid >> 1;            // 0..127
    const int cb = (tid & 1) * 64;      // 0 or 64
    const int tg = m0 + r;              // global token
    float* crow = C + (size_t)tg * N + n0 + cb;
    __nv_bfloat16* ghi = (mode == MODE_K) ? g_k_hi : g_v_hi;
    __nv_bfloat16* glo = (mode == MODE_K) ? g_k_lo : g_v_lo;
    const size_t ob = (size_t)tg * (NHKV * DHD) + n0 + cb;

#pragma unroll 1
    for (int c0 = 0; c0 < 64; c0 += 16) {
        float out[16];
#pragma unroll
        for (int c = 0; c < 16; c++) {
            float x = tile[r * 128 + cb + c0 + c];
            if (mode == MODE_V) {
                out[c] = x;
            } else {
                float p = tile[r * 128 + ((cb + c0 + c) ^ 64)];
                float cs, sn;
                sincosf((float)tg * g_invf[c0 + c], &sn, &cs);
                out[c] = cb ? (x * cs + p * sn) : (x * cs - p * sn);
            }
        }
#pragma unroll
        for (int c = 0; c < 16; c += 4)
            *(float4*)(crow + c0 + c) = make_float4(out[c], out[c+1], out[c+2], out[c+3]);
        if (mode != MODE_Q) {
#pragma unroll
            for (int c = 0; c < 16; c += 2) {
                uint32_t h, l;
                packhl(out[c], out[c + 1], h, l);
                *(uint32_t*)(ghi + ob + c0 + c) = h;
                *(uint32_t*)(glo + ob + c0 + c) = l;
            }
        }
    }
}

// ======== fat phase 1: all-HMMA — K/V (z=0) + Wq (z=1,2), fused RoPE =======
__global__ __launch_bounds__(256, 1)
void fat_phase1(const __nv_bfloat16* __restrict__ hsH, const __nv_bfloat16* __restrict__ hsL,
                const __nv_bfloat16* __restrict__ WqH, const __nv_bfloat16* __restrict__ WqL,
                const __nv_bfloat16* __restrict__ WkH, const __nv_bfloat16* __restrict__ WkL,
                const __nv_bfloat16* __restrict__ WvH, const __nv_bfloat16* __restrict__ WvL) {
    extern __shared__ char smraw[];
    if (blockIdx.z == 0) {
        int id = blockIdx.y * 32 + blockIdx.x;       // 0..255
        const bool isV = (id & 128) != 0;
        const __nv_bfloat16* BH = isV ? WvH : WkH;
        const __nv_bfloat16* BL = isV ? WvL : WkL;
        float* Cp = isV ? g_V : g_K;
        int mm = (id >> 3) & 15, nn = id & 7;
        gemm_body(hsH, hsL, BH, BL, Cp, 1024, 4096, nn, mm, smraw,
                  isV ? MODE_V : MODE_K);
    } else {
        int id = (blockIdx.z - 1) * 256 + blockIdx.y * 32 + blockIdx.x;  // 0..511
        int mm = id >> 5, nn = id & 31;
        gemm_body(hsH, hsL, WqH, WqL, g_Q, 4096, 4096, nn, mm, smraw, MODE_Q);
    }
}

// ============== flash attention body (bf16 hi/lo, mma.sync) ================
#define ATT_SMEM (65536 + 2 * 65536)

__device__ __forceinline__ void attn_load_kv(uint32_t stb, int t0, int hkv, int tid) {
    const int ch = tid & 7, rl = (tid >> 3) & 31;
#pragma unroll
    for (int s = 0; s < 2; s++) {
#pragma unroll
        for (int i = 0; i < 2; i++) {
            int r = rl + i * 32;
            uint32_t sp = stb + s * 8192 + r * 128 + ((ch ^ (r & 7)) << 4);
            size_t go = (size_t)(t0 + r) * (NHKV * DHD) + hkv * DHD + s * 64 + ch * 8;
            CP_ASYNC16(sp,         (const void*)(g_k_hi + go));
            CP_ASYNC16(sp + 16384, (const void*)(g_k_lo + go));
            CP_ASYNC16(sp + 32768, (const void*)(g_v_hi + go));
            CP_ASYNC16(sp + 49152, (const void*)(g_v_lo + go));
        }
    }
}

__device__ void attn_body(char* smraw) {
    const uint32_t sb = smem_u32(smraw);
    const int by = blockIdx.y;
    const int hkv = by >> 1;
    const int h0 = hkv * 4 + (by & 1) * 2;
    const int bq = 31 - blockIdx.x;            // LPT
    const int q0 = bq * 64;
    const int tid = threadIdx.x, lane = tid & 31, w = tid >> 5;
    const int whead = w >> 2, wq = w & 3;
    const int h = h0 + whead;
    const int lrow = ((lane >> 3) & 1) * 8 + (lane & 7);
    const int lkc  = lane >> 4;
    const int r1   = lane >> 2, colb = (lane & 3) * 2;

#pragma unroll
    for (int ii = 0; ii < 8; ii++) {
        int idx = tid + ii * 256;
        int ch = idx & 7, r = (idx >> 3) & 63, s = (idx >> 9) & 1, hh = idx >> 10;
        const float4* gp = (const float4*)(g_Q + (size_t)(q0 + r) * (NHQ * DHD)
                                           + (h0 + hh) * DHD + s * 64 + ch * 8);
        float4 f0 = gp[0], f1 = gp[1];
        uint32_t a0, a1, a2, a3, b0, b1, b2, b3;
        packhl(f0.x, f0.y, a0, b0);
        packhl(f0.z, f0.w, a1, b1);
        packhl(f1.x, f1.y, a2, b2);
        packhl(f1.z, f1.w, a3, b3);
        uint32_t off = hh * 32768 + s * 8192 + r * 128 + ((ch ^ (r & 7)) << 4);
        *(uint4*)(smraw + off)         = make_uint4(a0, a1, a2, a3);
        *(uint4*)(smraw + 16384 + off) = make_uint4(b0, b1, b2, b3);
    }

    const int qrow = wq * 16 + lrow;
    const uint32_t qbase = sb + whead * 32768;
    const int qrb  = qrow * 128, qr7 = qrow & 7;
    int kb[4], k7[4], vb[4], v7[4];
#pragma unroll
    for (int g = 0; g < 4; g++) {
        int kr = g * 16 + lrow;
        kb[g] = kr * 128; k7[g] = kr & 7;
        vb[g] = kb[g];    v7[g] = k7[g];
    }

    float m_i[2] = {-1e30f, -1e30f}, l_i[2] = {0.f, 0.f};
    float oacc[16][4];
#pragma unroll
    for (int g = 0; g < 16; g++)
#pragma unroll
        for (int e = 0; e < 4; e++) oacc[g][e] = 0.f;

    attn_load_kv(sb + 65536, 0, hkv, tid);
    CP_COMMIT();

    const int ntile = bq + 1;
    for (int kt = 0; kt < ntile; kt++) {
        CP_WAIT0();
        __syncthreads();
        if (kt + 1 < ntile) {
            attn_load_kv(sb + 65536 + ((kt + 1) & 1) * 65536, (kt + 1) * 64, hkv, tid);
            CP_COMMIT();
        }
        const uint32_t stg = sb + 65536 + (kt & 1) * 65536;

        float sacc[8][4];
#pragma unroll
        for (int nb = 0; nb < 8; nb++)
#pragma unroll
            for (int e = 0; e < 4; e++) sacc[nb][e] = 0.f;

#pragma unroll
        for (int sub = 0; sub < 2; sub++)
#pragma unroll
            for (int kk = 0; kk < 4; kk++) {
                const int kc = kk * 2 + lkc;
                uint32_t qoff = qbase + sub * 8192 + qrb + ((kc ^ qr7) << 4);
                uint32_t ah[4], al[4];
                ldmx4(qoff, ah);
                ldmx4(qoff + 16384, al);
#pragma unroll
                for (int ng = 0; ng < 4; ng++) {
                    uint32_t koff = stg + sub * 8192 + kb[ng] + ((kc ^ k7[ng]) << 4);
                    uint32_t bh[4], bl[4];
                    ldmx4(koff, bh);
                    ldmx4(koff + 16384, bl);
                    mma16816(sacc[ng * 2],     ah, bh[0], bh[2]);
                    mma16816(sacc[ng * 2 + 1], ah, bh[1], bh[3]);
                    mma16816(sacc[ng * 2],     ah, bl[0], bl[2]);
                    mma16816(sacc[ng * 2 + 1], ah, bl[1], bl[3]);
                    mma16816(sacc[ng * 2],     al, bh[0], bh[2]);
                    mma16816(sacc[ng * 2 + 1], al, bh[1], bh[3]);
                }
            }

        const bool diag = (kt == bq);
#pragma unroll
        for (int ri = 0; ri < 2; ri++) {
            const int rq = wq * 16 + r1 + ri * 8;
            float rm = -1e30f;
#pragma unroll
            for (int nb = 0; nb < 8; nb++)
#pragma unroll
                for (int e = 0; e < 2; e++) {
                    float v = sacc[nb][ri * 2 + e] * SM_SCALE;
                    if (diag && (nb * 8 + colb + e) > rq) v = -1e30f;
                    sacc[nb][ri * 2 + e] = v;
                    rm = fmaxf(rm, v);
                }
            rm = fmaxf(rm, __shfl_xor_sync(0xffffffffu, rm, 1));
            rm = fmaxf(rm, __shfl_xor_sync(0xffffffffu, rm, 2));
            float mnew = fmaxf(m_i[ri], rm);
            float corr = __expf(m_i[ri] - mnew);
            float ps = 0.f;
#pragma unroll
            for (int nb = 0; nb < 8; nb++)
#pragma unroll
                for (int e = 0; e < 2; e++) {
                    float p = __expf(sacc[nb][ri * 2 + e] - mnew);
                    sacc[nb][ri * 2 + e] = p;
                    ps += p;
                }
            ps += __shfl_xor_sync(0xffffffffu, ps, 1);
            ps += __shfl_xor_sync(0xffffffffu, ps, 2);
            l_i[ri] = l_i[ri] * corr + ps;
            m_i[ri] = mnew;
#pragma unroll
            for (int g = 0; g < 16; g++) {
                oacc[g][ri * 2]     *= corr;
                oacc[g][ri * 2 + 1] *= corr;
            }
        }

        uint32_t ph[4][4], pl[4][4];
#pragma unroll
        for (int j = 0; j < 4; j++) {
            packhl(sacc[2 * j][0],     sacc[2 * j][1],     ph[j][0], pl[j][0]);
            packhl(sacc[2 * j][2],     sacc[2 * j][3],     ph[j][1], pl[j][1]);
            packhl(sacc[2 * j + 1][0], sacc[2 * j + 1][1], ph[j][2], pl[j][2]);
            packhl(sacc[2 * j + 1][2], sacc[2 * j + 1][3], ph[j][3], pl[j][3]);
        }

#pragma unroll
        for (int j = 0; j < 4; j++)
#pragma unroll
            for (int g = 0; g < 8; g++) {
                const int sub = g >> 2, ch = (g & 3) * 2 + lkc;
                uint32_t voff = stg + 32768 + sub * 8192 + vb[j] + ((ch ^ v7[j]) << 4);
                uint32_t bh[4], bl[4];
                ldmx4t(voff, bh);
                ldmx4t(voff + 16384, bl);
                mma16816(oacc[2 * g],     ph[j], bh[0], bh[1]);
                mma16816(oacc[2 * g + 1], ph[j], bh[2], bh[3]);
                mma16816(oacc[2 * g],     ph[j], bl[0], bl[1]);
                mma16816(oacc[2 * g + 1], ph[j], bl[2], bl[3]);
                mma16816(oacc[2 * g],     pl[j], bh[0], bh[1]);
                mma16816(oacc[2 * g + 1], pl[j], bh[2], bh[3]);
            }
    }

    const float inv0 = 1.f / l_i[0], inv1 = 1.f / l_i[1];
    const int row0 = q0 + wq * 16 + r1;
#pragma unroll
    for (int g = 0; g < 16; g++) {
        size_t i0 = ((size_t)row0 * (NHQ * DHD) + h * DHD + g * 8 + colb) >> 1;
        size_t i1 = ((size_t)(row0 + 8) * (NHQ * DHD) + h * DHD + g * 8 + colb) >> 1;
        uint32_t h0r, l0r, h1r, l1r;
        packhl(oacc[g][0] * inv0, oacc[g][1] * inv0, h0r, l0r);
        packhl(oacc[g][2] * inv1, oacc[g][3] * inv1, h1r, l1r);
        ((uint32_t*)g_cx_hi)[i0] = h0r;
        ((uint32_t*)g_cx_lo)[i0] = l0r;
        ((uint32_t*)g_cx_hi)[i1] = h1r;
        ((uint32_t*)g_cx_lo)[i1] = l1r;
    }
}

// ---------------- rel body (256 threads, verbatim math) --------------------
__device__ void rel_body(int h) {
    const int r = blockIdx.x;
    const int qr = TT - GSZ + r;
    const int hkv = h >> 2;
    __shared__ float qrow[128];
    __shared__ float sc[TT];
    __shared__ float red[256];
    const int tid = threadIdx.x;

    if (tid < 128)
        qrow[tid] = g_Q[(size_t)qr * (NHQ * DHD) + h * DHD + tid];
    __syncthreads();

    const int n = qr + 1;
    for (int t = tid; t < n; t += 256) {
        const float* kp = g_K + (size_t)t * (NHKV * DHD) + hkv * DHD;
        float s = 0.f;
#pragma unroll
        for (int d4 = 0; d4 < 32; d4++) {
            float4 kv = *(const float4*)(kp + d4 * 4);
            float4 qv = *(const float4*)(qrow + d4 * 4);
            s += qv.x * kv.x + qv.y * kv.y + qv.z * kv.z + qv.w * kv.w;
        }
        sc[t] = s * SM_SCALE;
    }
    __syncthreads();

    float m = -1e30f;
    for (int t = tid; t < n; t += 256) m = fmaxf(m, sc[t]);
    red[tid] = m; __syncthreads();
    for (int s2 = 128; s2; s2 >>= 1) {
        if (tid < s2) red[tid] = fmaxf(red[tid], red[tid + s2]);
        __syncthreads();
    }
    m = red[0]; __syncthreads();

    float ls = 0.f;
    for (int t = tid; t < n; t += 256) ls += __expf(sc[t] - m);
    red[tid] = ls; __syncthreads();
    for (int s2 = 128; s2; s2 >>= 1) {
        if (tid < s2) red[tid] += red[tid + s2];
        __syncthreads();
    }
    const float linv = 1.f / red[0];

    for (int t = tid; t < n; t += 256)
        atomicAdd(&g_rel[hkv * TT + t], __expf(sc[t] - m) * linv);
}

// --------- K pruning with fp32 boundary repair (warp per row) --------------
__device__ void prune_k_rows(float* __restrict__ outK, const float* __restrict__ hs,
                             const float* __restrict__ Wk, int gw, int stride, int nloops) {
    const int w = threadIdx.x >> 5, lane = threadIdx.x & 31;
    __shared__ float buf[8][128];
    for (int it = 0; it < nloops; it++) {
        const int row = gw + it * stride;
        const int hkv = row >> 11, t = row & (TT - 1);
        const float* kp = g_K + (size_t)t * (NHKV * DHD) + hkv * DHD;
        float v[4], a[4];
#pragma unroll
        for (int q = 0; q < 4; q++) {
            v[q] = kp[q * 32 + lane];
            a[q] = fabsf(v[q]);
            buf[w][q * 32 + lane] = a[q];
        }
        __syncwarp();
        float cand = -1.f;
#pragma unroll
        for (int q = 0; q < 4; q++) {
            int clt = 0, cle = 0;
            for (int j = 0; j < 128; j++) {
                float x = buf[w][j];
                clt += (x < a[q]);
                cle += (x <= a[q]);
            }
            if (clt <= 63 && 63 < cle) cand = a[q];
        }
#pragma unroll
        for (int off = 16; off; off >>= 1)
            cand = fmaxf(cand, __shfl_xor_sync(0xffffffffu, cand, off));

        uint32_t nb[4];
        int ncnt = 0;
#pragma unroll
        for (int q = 0; q < 4; q++) {
            nb[q] = __ballot_sync(0xffffffffu, fabsf(a[q] - cand) < KMARG);
            ncnt += __popc(nb[q]);
        }
        if (ncnt >= 2) {
            const float* hsrow = hs + (size_t)t * HIDD;
#pragma unroll
            for (int q = 0; q < 4; q++) {
                uint32_t bits = nb[q];
                while (bits) {
                    int ln = __ffs(bits) - 1;
                    bits &= bits - 1;
                    int d  = q * 32 + ln;
                    int dd = d & 63;
                    int d2 = (d < 64) ? d + 64 : d - 64;
                    float s1 = coop_dot(hsrow, Wk + (size_t)(hkv * DHD + d)  * HIDD, lane);
                    float s2 = coop_dot(hsrow, Wk + (size_t)(hkv * DHD + d2) * HIDD, lane);
                    float c, s;
                    sincosf((float)t * g_invf[dd], &s, &c);
                    float ex = (d < 64) ? (s1 * c - s2 * s) : (s1 * c + s2 * s);
                    if (lane == ln) {
                        v[q] = ex;
                        a[q] = fabsf(ex);
                        buf[w][d] = a[q];
                    }
                }
            }
            __syncwarp();
            cand = -1.f;
#pragma unroll
            for (int q = 0; q < 4; q++) {
                int clt = 0, cle = 0;
                for (int j = 0; j < 128; j++) {
                    float x = buf[w][j];
                    clt += (x < a[q]);
                    cle += (x <= a[q]);
                }
                if (clt <= 63 && 63 < cle) cand = a[q];
            }
#pragma unroll
            for (int off = 16; off; off >>= 1)
                cand = fmaxf(cand, __shfl_xor_sync(0xffffffffu, cand, off));
        }

        float* op = outK + (size_t)row * DHD;
#pragma unroll
        for (int q = 0; q < 4; q++)
            op[q * 32 + lane] = (a[q] >= cand) ? v[q] : 0.f;
        __syncwarp();
    }
}

// --------- V pruning with fp32 boundary repair ------------------------------
__device__ void prune_v_rows(float* __restrict__ outV, const float* __restrict__ hs,
                             const float* __restrict__ Wv, int gw, int stride, int nloops) {
    const int w = threadIdx.x >> 5, lane = threadIdx.x & 31;
    __shared__ float buf[8][128];
    for (int it = 0; it < nloops; it++) {
        const int row = gw + it * stride;
        const int hkv = row >> 11, t = row & (TT - 1);
        const float* vp = g_V + (size_t)t * (NHKV * DHD) + hkv * DHD;
        float* op = outV + (size_t)row * DHD;
        float v[4];
#pragma unroll
        for (int q = 0; q < 4; q++) v[q] = vp[q * 32 + lane];

        if (t >= TT - GSZ) {
#pragma unroll
            for (int q = 0; q < 4; q++) op[q * 32 + lane] = v[q];
            continue;
        }
        const float rel = g_rel[hkv * TT + t];
        float sc[4];
#pragma unroll
        for (int q = 0; q < 4; q++) {
            sc[q] = fabsf(rel * v[q]);
            buf[w][q * 32 + lane] = sc[q];
        }
        __syncwarp();
        float cand = -1.f;
#pragma unroll
        for (int q = 0; q < 4; q++) {
            int clt = 0, cle = 0;
            for (int j = 0; j < 128; j++) {
                float x = buf[w][j];
                clt += (x < sc[q]);
                cle += (x <= sc[q]);
            }
            if (clt <= 64 && 64 < cle) cand = sc[q];
        }
#pragma unroll
        for (int off = 16; off; off >>= 1)
            cand = fmaxf(cand, __shfl_xor_sync(0xffffffffu, cand, off));

        const float marg = rel * VMARG;
        uint32_t nb[4];
        int ncnt = 0;
#pragma unroll
        for (int q = 0; q < 4; q++) {
            nb[q] = __ballot_sync(0xffffffffu, fabsf(sc[q] - cand) < marg);
            ncnt += __popc(nb[q]);
        }
        if (ncnt >= 2) {
            const float* hsrow = hs + (size_t)t * HIDD;
#pragma unroll
            for (int q = 0; q < 4; q++) {
                uint32_t bits = nb[q];
                while (bits) {
                    int ln = __ffs(bits) - 1;
                    bits &= bits - 1;
                    int d = q * 32 + ln;
                    float ex = coop_dot(hsrow, Wv + (size_t)(hkv * DHD + d) * HIDD, lane);
                    if (lane == ln) {
                        v[q] = ex;
                        sc[q] = fabsf(rel * ex);
                        buf[w][d] = sc[q];
                    }
                }
            }
            __syncwarp();
            cand = -1.f;
#pragma unroll
            for (int q = 0; q < 4; q++) {
                int clt = 0, cle = 0;
                for (int j = 0; j < 128; j++) {
                    float x = buf[w][j];
                    clt += (x < sc[q]);
                    cle += (x <= sc[q]);
                }
                if (clt <= 64 && 64 < cle) cand = sc[q];
            }
#pragma unroll
            for (int off = 16; off; off >>= 1)
                cand = fmaxf(cand, __shfl_xor_sync(0xffffffffu, cand, off));
        }

#pragma unroll
        for (int q = 0; q < 4; q++)
            op[q * 32 + lane] = (sc[q] >= cand) ? v[q] : 0.f;
        __syncwarp();
    }
}

// === fat phase 2: attn 2-head (z=0) + rel (z=1,2) + prune_k (z=3) ==========
__global__ __launch_bounds__(256, 1)
void fat_phase2(float* __restrict__ outK, const float* __restrict__ hs,
                const float* __restrict__ Wk) {
    extern __shared__ char smraw[];
    if (blockIdx.z == 0) {
        attn_body(smraw);
    } else if (blockIdx.z < 3) {
        rel_body((blockIdx.z - 1) * 16 + blockIdx.y);
    } else {
        const int gw = (blockIdx.y * 32 + blockIdx.x) * 8 + (threadIdx.x >> 5);
        prune_k_rows(outK, hs, Wk, gw, 4096, 4);
    }
}

// ======== fat phase 3: Wo bf16x3 HMMA (z=0) + prune_v (z=1) ================
__global__ __launch_bounds__(256, 1)
void fat_phase3(const __nv_bfloat16* __restrict__ cxH, const __nv_bfloat16* __restrict__ cxL,
                const __nv_bfloat16* __restrict__ WoH, const __nv_bfloat16* __restrict__ WoL,
                float* __restrict__ outA, float* __restrict__ outV,
                const float* __restrict__ hs, const float* __restrict__ Wv) {
    extern __shared__ char smraw[];
    if (blockIdx.z == 0) {
        gemm_body(cxH, cxL, WoH, WoL, outA, 4096, 4096, blockIdx.x, blockIdx.y,
                  smraw, MODE_PLAIN);
    } else {
        const int gw = (blockIdx.y * 32 + blockIdx.x) * 8 + (threadIdx.x >> 5);
        prune_v_rows(outV, hs, Wv, gw, 4096, 4);
    }
}

// ---------------- launcher -------------------------------------------------
extern "C" void kernel_launch(void* const* d_in, const int* in_sizes, int n_in,
                              void* d_out, int out_size) {
    const float* hs = (const float*)d_in[0];
    const float* Wq = (const float*)d_in[1];
    const float* Wk = (const float*)d_in[2];
    const float* Wv = (const float*)d_in[3];
    const float* Wo = (const float*)d_in[4];

    float* outA = (float*)d_out;
    float* outK = outA + (size_t)TT * HIDD;
    float* outV = outK + (size_t)NHKV * TT * DHD;

    __nv_bfloat16 *hsH, *hsL, *cxH, *cxL, *WqH, *WqL, *WoH, *WoL;
    __nv_bfloat16 *WkH, *WkL, *WvH, *WvL;
    cudaGetSymbolAddress((void**)&hsH, g_hs_hi); cudaGetSymbolAddress((void**)&hsL, g_hs_lo);
    cudaGetSymbolAddress((void**)&cxH, g_cx_hi); cudaGetSymbolAddress((void**)&cxL, g_cx_lo);
    cudaGetSymbolAddress((void**)&WqH, g_Wq_hi); cudaGetSymbolAddress((void**)&WqL, g_Wq_lo);
    cudaGetSymbolAddress((void**)&WoH, g_Wo_hi); cudaGetSymbolAddress((void**)&WoL, g_Wo_lo);
    cudaGetSymbolAddress((void**)&WkH, g_Wk_hi); cudaGetSymbolAddress((void**)&WkL, g_Wk_lo);
    cudaGetSymbolAddress((void**)&WvH, g_Wv_hi); cudaGetSymbolAddress((void**)&WvL, g_Wv_lo);

    cudaFuncSetAttribute(fat_phase1, cudaFuncAttributeMaxDynamicSharedMemorySize, GEMM_SMEM);
    cudaFuncSetAttribute(fat_phase2, cudaFuncAttributeMaxDynamicSharedMemorySize, ATT_SMEM);
    cudaFuncSetAttribute(fat_phase3, cudaFuncAttributeMaxDynamicSharedMemorySize, GEMM_SMEM);

    // fused splits + invfreq init + g_rel zero (one BW-bound launch)
    split_all_kernel<<<SPL_HALF / 256, 256>>>(hs, Wq, Wo, Wk, Wv);

    // Phase 1: all projections on tensor cores; RoPE + K/V splits fused in epilogues
    fat_phase1<<<dim3(32, 8, 3), 256, GEMM_SMEM>>>(hsH, hsL, WqH, WqL, WkH, WkL, WvH, WvL);

    // Phase 2: attention + rel + prune_k (fp32 boundary repair)
    fat_phase2<<<dim3(32, 16, 4), 256, ATT_SMEM>>>(outK, hs, Wk);

    // Phase 3: Wo HMMA + prune_v (fp32 boundary repair)
    fat_phase3<<<dim3(32, 16, 2), 256, GEMM_SMEM>>>(cxH, cxL, WoH, WoL, outA, outV, hs, Wv);
}

// round 17
// speedup vs baseline: 1.0347x; 1.0347x over previous
#include <cuda_runtime.h>
#include <cuda_bf16.h>
#include <cmath>
#include <cstdint>

#define TT    2048
#define HIDD  4096
#define NHQ   32
#define NHKV  8
#define DHD   128
#define GSZ   32
#define SM_SCALE 0.088388347648318447f   // 1/sqrt(128)
#define KMARG 1.5e-3f
#define VMARG 1.5e-3f

// ---------------- device scratch (no runtime allocation allowed) ----------
__device__ float g_Q[TT * NHQ * DHD];
__device__ float g_K[TT * NHKV * DHD];
__device__ float g_V[TT * NHKV * DHD];
__device__ float g_rel[NHKV * TT];
__device__ float g_invf[64];

// bf16 split copies
__device__ __nv_bfloat16 g_hs_hi[TT * HIDD],  g_hs_lo[TT * HIDD];
__device__ __align__(16) __nv_bfloat16 g_cx_hi[TT * HIDD],  g_cx_lo[TT * HIDD];
__device__ __nv_bfloat16 g_Wq_hi[HIDD * HIDD], g_Wq_lo[HIDD * HIDD];
__device__ __nv_bfloat16 g_Wo_hi[HIDD * HIDD], g_Wo_lo[HIDD * HIDD];
__device__ __nv_bfloat16 g_Wk_hi[NHKV * DHD * HIDD], g_Wk_lo[NHKV * DHD * HIDD];
__device__ __nv_bfloat16 g_Wv_hi[NHKV * DHD * HIDD], g_Wv_lo[NHKV * DHD * HIDD];
__device__ __align__(16) __nv_bfloat16 g_k_hi[TT * NHKV * DHD], g_k_lo[TT * NHKV * DHD];
__device__ __align__(16) __nv_bfloat16 g_v_hi[TT * NHKV * DHD], g_v_lo[TT * NHKV * DHD];

// ======================= PTX helpers (plain sm_80+ ops only) ===============
__device__ __forceinline__ uint32_t smem_u32(const void* p) {
    uint32_t a;
    asm("{ .reg .u64 t; cvta.to.shared.u64 t, %1; cvt.u32.u64 %0, t; }" : "=r"(a) : "l"(p));
    return a;
}
#define CP_ASYNC16(dst, src) \
    asm volatile("cp.async.cg.shared.global [%0], [%1], 16;" :: "r"(dst), "l"(src) : "memory")
#define CP_COMMIT() asm volatile("cp.async.commit_group;" ::: "memory")
#define CP_WAIT1()  asm volatile("cp.async.wait_group 1;" ::: "memory")
#define CP_WAIT0()  asm volatile("cp.async.wait_group 0;" ::: "memory")

__device__ __forceinline__ void ldmx4(uint32_t addr, uint32_t* r) {
    asm volatile("ldmatrix.sync.aligned.m8n8.x4.shared.b16 {%0,%1,%2,%3}, [%4];"
                 : "=r"(r[0]), "=r"(r[1]), "=r"(r[2]), "=r"(r[3]) : "r"(addr));
}
__device__ __forceinline__ void ldmx4t(uint32_t addr, uint32_t* r) {
    asm volatile("ldmatrix.sync.aligned.m8n8.x4.trans.shared.b16 {%0,%1,%2,%3}, [%4];"
                 : "=r"(r[0]), "=r"(r[1]), "=r"(r[2]), "=r"(r[3]) : "r"(addr));
}
__device__ __forceinline__ void mma16816(float* d, const uint32_t* a,
                                         uint32_t b0, uint32_t b1) {
    asm volatile(
        "mma.sync.aligned.m16n8k16.row.col.f32.bf16.bf16.f32 "
        "{%0,%1,%2,%3}, {%4,%5,%6,%7}, {%8,%9}, {%0,%1,%2,%3};"
        : "+f"(d[0]), "+f"(d[1]), "+f"(d[2]), "+f"(d[3])
        : "r"(a[0]), "r"(a[1]), "r"(a[2]), "r"(a[3]), "r"(b0), "r"(b1));
}

__device__ __forceinline__ void packhl(float x, float y, uint32_t& hi, uint32_t& lo) {
    __nv_bfloat16 hx = __float2bfloat16(x), hy = __float2bfloat16(y);
    __nv_bfloat162 h2(hx, hy);
    hi = *(uint32_t*)&h2;
    __nv_bfloat162 l2(__float2bfloat16(x - __bfloat162float(hx)),
                      __float2bfloat16(y - __bfloat162float(hy)));
    lo = *(uint32_t*)&l2;
}

// warp-cooperative exact fp32 dot of two 4096-vectors
__device__ __forceinline__ float coop_dot(const float* __restrict__ a,
                                          const float* __restrict__ b, int lane) {
    float s = 0.f;
    for (int kk = lane * 4; kk < HIDD; kk += 128) {
        float4 av = *(const float4*)(a + kk);
        float4 bv = *(const float4*)(b + kk);
        s = fmaf(av.x, bv.x, s);
        s = fmaf(av.y, bv.y, s);
        s = fmaf(av.z, bv.z, s);
        s = fmaf(av.w, bv.w, s);
    }
#pragma unroll
    for (int off = 16; off; off >>= 1)
        s += __shfl_xor_sync(0xffffffffu, s, off);
    return s;
}

// ------------- fused split + invfreq init + rel zero -----------------------
#define SPL_C0 2097152     // hs  (TT*HIDD/4)
#define SPL_C1 6291456     // +Wq (HIDD*HIDD/4)
#define SPL_C2 10485760    // +Wo
#define SPL_C3 11534336    // +Wk (NHKV*DHD*HIDD/4)
#define SPL_C4 12582912    // +Wv
#define SPL_HALF (SPL_C4 / 2)

__device__ __forceinline__ void split_one(const float* hs, const float* Wq,
                                          const float* Wo, const float* Wk,
                                          const float* Wv, int i) {
    const float* src;
    __nv_bfloat16 *hi, *lo;
    int off;
    if (i < SPL_C0)      { src = hs; hi = g_hs_hi; lo = g_hs_lo; off = i; }
    else if (i < SPL_C1) { src = Wq; hi = g_Wq_hi; lo = g_Wq_lo; off = i - SPL_C0; }
    else if (i < SPL_C2) { src = Wo; hi = g_Wo_hi; lo = g_Wo_lo; off = i - SPL_C1; }
    else if (i < SPL_C3) { src = Wk; hi = g_Wk_hi; lo = g_Wk_lo; off = i - SPL_C2; }
    else                 { src = Wv; hi = g_Wv_hi; lo = g_Wv_lo; off = i - SPL_C3; }
    float4 v = ((const float4*)src)[off];
    uint32_t h0, h1, l0, l1;
    packhl(v.x, v.y, h0, l0);
    packhl(v.z, v.w, h1, l1);
    ((uint32_t*)hi)[off * 2]     = h0;
    ((uint32_t*)hi)[off * 2 + 1] = h1;
    ((uint32_t*)lo)[off * 2]     = l0;
    ((uint32_t*)lo)[off * 2 + 1] = l1;
}

__global__ __launch_bounds__(256)
void split_all_kernel(const float* __restrict__ hs, const float* __restrict__ Wq,
                      const float* __restrict__ Wo, const float* __restrict__ Wk,
                      const float* __restrict__ Wv) {
    if (blockIdx.x == 0 && threadIdx.x < 64)
        g_invf[threadIdx.x] = (float)(1.0 / pow(10000.0, (double)threadIdx.x / 64.0));
    if (blockIdx.x < 64)
        g_rel[blockIdx.x * 256 + threadIdx.x] = 0.f;
    int i = blockIdx.x * 256 + threadIdx.x;
    split_one(hs, Wq, Wo, Wk, Wv, i);
    split_one(hs, Wq, Wo, Wk, Wv, i + SPL_HALF);
}

// ============ bf16x3 HMMA GEMM body (round-15 champion, no modes) ==========
#define GBK     64
#define GTILEB  (128 * 128)
#define GSTAGEB (4 * GTILEB)
#define GEMM_SMEM (3 * GSTAGEB)          // 192 KB dynamic

__device__ __forceinline__ void load_tile(uint32_t st, const __nv_bfloat16* g,
                                          int row0, int k0, int pitch,
                                          int ch, int rl) {
    const char* gp = (const char*)(g + (size_t)(row0 + rl) * pitch + k0 + ch * 8);
    const size_t gstep = (size_t)32 * pitch * sizeof(__nv_bfloat16);
#pragma unroll
    for (int i = 0; i < 4; i++) {
        int row = rl + i * 32;
        uint32_t sp = st + row * 128 + ((ch ^ (row & 7)) << 4);
        CP_ASYNC16(sp, gp);
        gp += gstep;
    }
}

__device__ void gemm_body(const __nv_bfloat16* __restrict__ Ahi, const __nv_bfloat16* __restrict__ Alo,
                          const __nv_bfloat16* __restrict__ Bhi, const __nv_bfloat16* __restrict__ Blo,
                          float* __restrict__ C, int N, int K, int bx, int by, char* smraw) {
    const uint32_t sb = smem_u32(smraw);
    const int tid = threadIdx.x, lane = tid & 31, wid = tid >> 5;
    const int wm = wid & 3, wn = wid >> 2;
    const int m0 = by * 128, n0 = bx * 128;
    const int ch = tid & 7, rl = tid >> 3;

    float acc[2][8][4];
#pragma unroll
    for (int a = 0; a < 2; a++)
#pragma unroll
        for (int b = 0; b < 8; b++)
#pragma unroll
            for (int c = 0; c < 4; c++) acc[a][b][c] = 0.f;

    const int lm      = lane >> 3;
    const int lrow    = (lm & 1) * 8 + (lane & 7);
    const int lkchunk = lm >> 1;

    int arb[2], ar7[2], brb[4], br7[4];
#pragma unroll
    for (int mf = 0; mf < 2; mf++) {
        int r = wm * 32 + mf * 16 + lrow;
        arb[mf] = r * 128; ar7[mf] = r & 7;
    }
#pragma unroll
    for (int ng = 0; ng < 4; ng++) {
        int r = wn * 64 + ng * 16 + lrow;
        brb[ng] = r * 128; br7[ng] = r & 7;
    }

    const int nch = K / GBK;
    load_tile(sb,               Ahi, m0, 0, K, ch, rl);
    load_tile(sb +     GTILEB,  Alo, m0, 0, K, ch, rl);
    load_tile(sb + 2 * GTILEB,  Bhi, n0, 0, K, ch, rl);
    load_tile(sb + 3 * GTILEB,  Blo, n0, 0, K, ch, rl);
    CP_COMMIT();
    load_tile(sb + GSTAGEB,              Ahi, m0, GBK, K, ch, rl);
    load_tile(sb + GSTAGEB +     GTILEB, Alo, m0, GBK, K, ch, rl);
    load_tile(sb + GSTAGEB + 2 * GTILEB, Bhi, n0, GBK, K, ch, rl);
    load_tile(sb + GSTAGEB + 3 * GTILEB, Blo, n0, GBK, K, ch, rl);
    CP_COMMIT();

    for (int it = 0; it < nch; it++) {
        CP_WAIT1();
        __syncthreads();

        const uint32_t st  = sb + (it % 3) * GSTAGEB;
        const uint32_t tAh = st,              tAl = st + GTILEB;
        const uint32_t tBh = st + 2 * GTILEB, tBl = st + 3 * GTILEB;

#pragma unroll
        for (int kk = 0; kk < 4; kk++) {
            const int kc = kk * 2 + lkchunk;
            uint32_t ahi[2][4], alo[2][4];
#pragma unroll
            for (int mf = 0; mf < 2; mf++) {
                uint32_t off = arb[mf] + ((kc ^ ar7[mf]) << 4);
                ldmx4(tAh + off, ahi[mf]);
                ldmx4(tAl + off, alo[mf]);
            }
#pragma unroll
            for (int ng = 0; ng < 4; ng++) {
                uint32_t off = brb[ng] + ((kc ^ br7[ng]) << 4);
                uint32_t bh[4], bl[4];
                ldmx4(tBh + off, bh);
                ldmx4(tBl + off, bl);
#pragma unroll
                for (int mf = 0; mf < 2; mf++) {
                    mma16816(acc[mf][ng * 2],     ahi[mf], bh[0], bh[2]);
                    mma16816(acc[mf][ng * 2 + 1], ahi[mf], bh[1], bh[3]);
                    mma16816(acc[mf][ng * 2],     ahi[mf], bl[0], bl[2]);
                    mma16816(acc[mf][ng * 2 + 1], ahi[mf], bl[1], bl[3]);
                    mma16816(acc[mf][ng * 2],     alo[mf], bh[0], bh[2]);
                    mma16816(acc[mf][ng * 2 + 1], alo[mf], bh[1], bh[3]);
                }
            }
        }
        __syncthreads();

        const int cn = it + 2;
        if (cn < nch) {
            const uint32_t sn = sb + (cn % 3) * GSTAGEB;
            load_tile(sn,              Ahi, m0, cn * GBK, K, ch, rl);
            load_tile(sn +     GTILEB, Alo, m0, cn * GBK, K, ch, rl);
            load_tile(sn + 2 * GTILEB, Bhi, n0, cn * GBK, K, ch, rl);
            load_tile(sn + 3 * GTILEB, Blo, n0, cn * GBK, K, ch, rl);
        }
        CP_COMMIT();
    }

    const int er = m0 + wm * 32 + (lane >> 2);
    const int ec = n0 + wn * 64 + (lane & 3) * 2;
#pragma unroll
    for (int mf = 0; mf < 2; mf++)
#pragma unroll
        for (int nf = 0; nf < 8; nf++) {
            float* p0 = C + (size_t)(er + mf * 16) * N + ec + nf * 8;
            float* p1 = C + (size_t)(er + mf * 16 + 8) * N + ec + nf * 8;
            *(float2*)p0 = make_float2(acc[mf][nf][0], acc[mf][nf][1]);
            *(float2*)p1 = make_float2(acc[mf][nf][2], acc[mf][nf][3]);
        }
}

// ======== fat phase 1: all-HMMA — K/V (z=0) + Wq (z=1,2) ===================
__global__ __launch_bounds__(256, 1)
void fat_phase1(const __nv_bfloat16* __restrict__ hsH, const __nv_bfloat16* __restrict__ hsL,
                const __nv_bfloat16* __restrict__ WqH, const __nv_bfloat16* __restrict__ WqL,
                const __nv_bfloat16* __restrict__ WkH, const __nv_bfloat16* __restrict__ WkL,
                const __nv_bfloat16* __restrict__ WvH, const __nv_bfloat16* __restrict__ WvL) {
    extern __shared__ char smraw[];
    if (blockIdx.z == 0) {
        int id = blockIdx.y * 32 + blockIdx.x;       // 0..255
        const __nv_bfloat16* BH = (id & 128) ? WvH : WkH;
        const __nv_bfloat16* BL = (id & 128) ? WvL : WkL;
        float* C = (id & 128) ? g_V : g_K;
        int mm = (id >> 3) & 15, nn = id & 7;        // 16 m-tiles x 8 n-tiles
        gemm_body(hsH, hsL, BH, BL, C, 1024, 4096, nn, mm, smraw);
    } else {
        int id = (blockIdx.z - 1) * 256 + blockIdx.y * 32 + blockIdx.x;  // 0..511
        int mm = id >> 5, nn = id & 31;              // 16 m-tiles x 32 n-tiles
        gemm_body(hsH, hsL, WqH, WqL, g_Q, 4096, 4096, nn, mm, smraw);
    }
}

// ---------------- RoPE in place + fused K/V bf16 split ---------------------
__global__ __launch_bounds__(256)
void rope_kernel() {
    const int t = blockIdx.x;
    for (int idx = threadIdx.x; idx < (NHQ + NHKV) * 64; idx += 256) {
        int hh = idx >> 6, d = idx & 63;
        float ang = (float)t * g_invf[d];
        float c, s;
        sincosf(ang, &s, &c);
        if (hh < NHQ) {
            float* p = g_Q + (size_t)t * (NHQ * DHD) + hh * DHD;
            float x1 = p[d], x2 = p[d + 64];
            p[d]      = x1 * c - x2 * s;
            p[d + 64] = x2 * c + x1 * s;
        } else {
            size_t o = (size_t)t * (NHKV * DHD) + (hh - NHQ) * DHD;
            float x1 = g_K[o + d], x2 = g_K[o + d + 64];
            float y1 = x1 * c - x2 * s;
            float y2 = x2 * c + x1 * s;
            g_K[o + d]      = y1;
            g_K[o + d + 64] = y2;
            __nv_bfloat16 h1 = __float2bfloat16(y1);
            g_k_hi[o + d] = h1;
            g_k_lo[o + d] = __float2bfloat16(y1 - __bfloat162float(h1));
            __nv_bfloat16 h2 = __float2bfloat16(y2);
            g_k_hi[o + d + 64] = h2;
            g_k_lo[o + d + 64] = __float2bfloat16(y2 - __bfloat162float(h2));
        }
    }
    for (int idx = threadIdx.x; idx < NHKV * DHD; idx += 256) {
        size_t o = (size_t)t * (NHKV * DHD) + idx;
        float v = g_V[o];
        __nv_bfloat16 h = __float2bfloat16(v);
        g_v_hi[o] = h;
        g_v_lo[o] = __float2bfloat16(v - __bfloat162float(h));
    }
}

// ============== flash attention body (bf16 hi/lo, mma.sync) ================
#define ATT_SMEM (65536 + 2 * 65536)

__device__ __forceinline__ void attn_load_kv(uint32_t stb, int t0, int hkv, int tid) {
    const int ch = tid & 7, rl = (tid >> 3) & 31;
#pragma unroll
    for (int s = 0; s < 2; s++) {
#pragma unroll
        for (int i = 0; i < 2; i++) {
            int r = rl + i * 32;
            uint32_t sp = stb + s * 8192 + r * 128 + ((ch ^ (r & 7)) << 4);
            size_t go = (size_t)(t0 + r) * (NHKV * DHD) + hkv * DHD + s * 64 + ch * 8;
            CP_ASYNC16(sp,         (const void*)(g_k_hi + go));
            CP_ASYNC16(sp + 16384, (const void*)(g_k_lo + go));
            CP_ASYNC16(sp + 32768, (const void*)(g_v_hi + go));
            CP_ASYNC16(sp + 49152, (const void*)(g_v_lo + go));
        }
    }
}

__device__ void attn_body(char* smraw) {
    const uint32_t sb = smem_u32(smraw);
    const int by = blockIdx.y;
    const int hkv = by >> 1;
    const int h0 = hkv * 4 + (by & 1) * 2;
    const int bq = 31 - blockIdx.x;            // LPT
    const int q0 = bq * 64;
    const int tid = threadIdx.x, lane = tid & 31, w = tid >> 5;
    const int whead = w >> 2, wq = w & 3;
    const int h = h0 + whead;
    const int lrow = ((lane >> 3) & 1) * 8 + (lane & 7);
    const int lkc  = lane >> 4;
    const int r1   = lane >> 2, colb = (lane & 3) * 2;

#pragma unroll
    for (int ii = 0; ii < 8; ii++) {
        int idx = tid + ii * 256;
        int ch = idx & 7, r = (idx >> 3) & 63, s = (idx >> 9) & 1, hh = idx >> 10;
        const float4* gp = (const float4*)(g_Q + (size_t)(q0 + r) * (NHQ * DHD)
                                           + (h0 + hh) * DHD + s * 64 + ch * 8);
        float4 f0 = gp[0], f1 = gp[1];
        uint32_t a0, a1, a2, a3, b0, b1, b2, b3;
        packhl(f0.x, f0.y, a0, b0);
        packhl(f0.z, f0.w, a1, b1);
        packhl(f1.x, f1.y, a2, b2);
        packhl(f1.z, f1.w, a3, b3);
        uint32_t off = hh * 32768 + s * 8192 + r * 128 + ((ch ^ (r & 7)) << 4);
        *(uint4*)(smraw + off)         = make_uint4(a0, a1, a2, a3);
        *(uint4*)(smraw + 16384 + off) = make_uint4(b0, b1, b2, b3);
    }

    const int qrow = wq * 16 + lrow;
    const uint32_t qbase = sb + whead * 32768;
    const int qrb  = qrow * 128, qr7 = qrow & 7;
    int kb[4], k7[4], vb[4], v7[4];
#pragma unroll
    for (int g = 0; g < 4; g++) {
        int kr = g * 16 + lrow;
        kb[g] = kr * 128; k7[g] = kr & 7;
        vb[g] = kb[g];    v7[g] = k7[g];
    }

    float m_i[2] = {-1e30f, -1e30f}, l_i[2] = {0.f, 0.f};
    float oacc[16][4];
#pragma unroll
    for (int g = 0; g < 16; g++)
#pragma unroll
        for (int e = 0; e < 4; e++) oacc[g][e] = 0.f;

    attn_load_kv(sb + 65536, 0, hkv, tid);
    CP_COMMIT();

    const int ntile = bq + 1;
    for (int kt = 0; kt < ntile; kt++) {
        CP_WAIT0();
        __syncthreads();
        if (kt + 1 < ntile) {
            attn_load_kv(sb + 65536 + ((kt + 1) & 1) * 65536, (kt + 1) * 64, hkv, tid);
            CP_COMMIT();
        }
        const uint32_t stg = sb + 65536 + (kt & 1) * 65536;

        float sacc[8][4];
#pragma unroll
        for (int nb = 0; nb < 8; nb++)
#pragma unroll
            for (int e = 0; e < 4; e++) sacc[nb][e] = 0.f;

#pragma unroll
        for (int sub = 0; sub < 2; sub++)
#pragma unroll
            for (int kk = 0; kk < 4; kk++) {
                const int kc = kk * 2 + lkc;
                uint32_t qoff = qbase + sub * 8192 + qrb + ((kc ^ qr7) << 4);
                uint32_t ah[4], al[4];
                ldmx4(qoff, ah);
                ldmx4(qoff + 16384, al);
#pragma unroll
                for (int ng = 0; ng < 4; ng++) {
                    uint32_t koff = stg + sub * 8192 + kb[ng] + ((kc ^ k7[ng]) << 4);
                    uint32_t bh[4], bl[4];
                    ldmx4(koff, bh);
                    ldmx4(koff + 16384, bl);
                    mma16816(sacc[ng * 2],     ah, bh[0], bh[2]);
                    mma16816(sacc[ng * 2 + 1], ah, bh[1], bh[3]);
                    mma16816(sacc[ng * 2],     ah, bl[0], bl[2]);
                    mma16816(sacc[ng * 2 + 1], ah, bl[1], bl[3]);
                    mma16816(sacc[ng * 2],     al, bh[0], bh[2]);
                    mma16816(sacc[ng * 2 + 1], al, bh[1], bh[3]);
                }
            }

        const bool diag = (kt == bq);
#pragma unroll
        for (int ri = 0; ri < 2; ri++) {
            const int rq = wq * 16 + r1 + ri * 8;
            float rm = -1e30f;
#pragma unroll
            for (int nb = 0; nb < 8; nb++)
#pragma unroll
                for (int e = 0; e < 2; e++) {
                    float v = sacc[nb][ri * 2 + e] * SM_SCALE;
                    if (diag && (nb * 8 + colb + e) > rq) v = -1e30f;
                    sacc[nb][ri * 2 + e] = v;
                    rm = fmaxf(rm, v);
                }
            rm = fmaxf(rm, __shfl_xor_sync(0xffffffffu, rm, 1));
            rm = fmaxf(rm, __shfl_xor_sync(0xffffffffu, rm, 2));
            float mnew = fmaxf(m_i[ri], rm);
            float corr = __expf(m_i[ri] - mnew);
            float ps = 0.f;
#pragma unroll
            for (int nb = 0; nb < 8; nb++)
#pragma unroll
                for (int e = 0; e < 2; e++) {
                    float p = __expf(sacc[nb][ri * 2 + e] - mnew);
                    sacc[nb][ri * 2 + e] = p;
                    ps += p;
                }
            ps += __shfl_xor_sync(0xffffffffu, ps, 1);
            ps += __shfl_xor_sync(0xffffffffu, ps, 2);
            l_i[ri] = l_i[ri] * corr + ps;
            m_i[ri] = mnew;
#pragma unroll
            for (int g = 0; g < 16; g++) {
                oacc[g][ri * 2]     *= corr;
                oacc[g][ri * 2 + 1] *= corr;
            }
        }

        uint32_t ph[4][4], pl[4][4];
#pragma unroll
        for (int j = 0; j < 4; j++) {
            packhl(sacc[2 * j][0],     sacc[2 * j][1],     ph[j][0], pl[j][0]);
            packhl(sacc[2 * j][2],     sacc[2 * j][3],     ph[j][1], pl[j][1]);
            packhl(sacc[2 * j + 1][0], sacc[2 * j + 1][1], ph[j][2], pl[j][2]);
            packhl(sacc[2 * j + 1][2], sacc[2 * j + 1][3], ph[j][3], pl[j][3]);
        }

#pragma unroll
        for (int j = 0; j < 4; j++)
#pragma unroll
            for (int g = 0; g < 8; g++) {
                const int sub = g >> 2, ch = (g & 3) * 2 + lkc;
                uint32_t voff = stg + 32768 + sub * 8192 + vb[j] + ((ch ^ v7[j]) << 4);
                uint32_t bh[4], bl[4];
                ldmx4t(voff, bh);
                ldmx4t(voff + 16384, bl);
                mma16816(oacc[2 * g],     ph[j], bh[0], bh[1]);
                mma16816(oacc[2 * g + 1], ph[j], bh[2], bh[3]);
                mma16816(oacc[2 * g],     ph[j], bl[0], bl[1]);
                mma16816(oacc[2 * g + 1], ph[j], bl[2], bl[3]);
                mma16816(oacc[2 * g],     pl[j], bh[0], bh[1]);
                mma16816(oacc[2 * g + 1], pl[j], bh[2], bh[3]);
            }
    }

    const float inv0 = 1.f / l_i[0], inv1 = 1.f / l_i[1];
    const int row0 = q0 + wq * 16 + r1;
#pragma unroll
    for (int g = 0; g < 16; g++) {
        size_t i0 = ((size_t)row0 * (NHQ * DHD) + h * DHD + g * 8 + colb) >> 1;
        size_t i1 = ((size_t)(row0 + 8) * (NHQ * DHD) + h * DHD + g * 8 + colb) >> 1;
        uint32_t h0r, l0r, h1r, l1r;
        packhl(oacc[g][0] * inv0, oacc[g][1] * inv0, h0r, l0r);
        packhl(oacc[g][2] * inv1, oacc[g][3] * inv1, h1r, l1r);
        ((uint32_t*)g_cx_hi)[i0] = h0r;
        ((uint32_t*)g_cx_lo)[i0] = l0r;
        ((uint32_t*)g_cx_hi)[i1] = h1r;
        ((uint32_t*)g_cx_lo)[i1] = l1r;
    }
}

// ---------------- rel body (256 threads, verbatim math) --------------------
__device__ void rel_body(int h) {
    const int r = blockIdx.x;
    const int qr = TT - GSZ + r;
    const int hkv = h >> 2;
    __shared__ float qrow[128];
    __shared__ float sc[TT];
    __shared__ float red[256];
    const int tid = threadIdx.x;

    if (tid < 128)
        qrow[tid] = g_Q[(size_t)qr * (NHQ * DHD) + h * DHD + tid];
    __syncthreads();

    const int n = qr + 1;
    for (int t = tid; t < n; t += 256) {
        const float* kp = g_K + (size_t)t * (NHKV * DHD) + hkv * DHD;
        float s = 0.f;
#pragma unroll
        for (int d4 = 0; d4 < 32; d4++) {
            float4 kv = *(const float4*)(kp + d4 * 4);
            float4 qv = *(const float4*)(qrow + d4 * 4);
            s += qv.x * kv.x + qv.y * kv.y + qv.z * kv.z + qv.w * kv.w;
        }
        sc[t] = s * SM_SCALE;
    }
    __syncthreads();

    float m = -1e30f;
    for (int t = tid; t < n; t += 256) m = fmaxf(m, sc[t]);
    red[tid] = m; __syncthreads();
    for (int s2 = 128; s2; s2 >>= 1) {
        if (tid < s2) red[tid] = fmaxf(red[tid], red[tid + s2]);
        __syncthreads();
    }
    m = red[0]; __syncthreads();

    float ls = 0.f;
    for (int t = tid; t < n; t += 256) ls += __expf(sc[t] - m);
    red[tid] = ls; __syncthreads();
    for (int s2 = 128; s2; s2 >>= 1) {
        if (tid < s2) red[tid] += red[tid + s2];
        __syncthreads();
    }
    const float linv = 1.f / red[0];

    for (int t = tid; t < n; t += 256)
        atomicAdd(&g_rel[hkv * TT + t], __expf(sc[t] - m) * linv);
}

// --------- K pruning with fp32 boundary repair (warp per row) --------------
__device__ void prune_k_rows(float* __restrict__ outK, const float* __restrict__ hs,
                             const float* __restrict__ Wk, int gw, int stride, int nloops) {
    const int w = threadIdx.x >> 5, lane = threadIdx.x & 31;
    __shared__ float buf[8][128];
    for (int it = 0; it < nloops; it++) {
        const int row = gw + it * stride;
        const int hkv = row >> 11, t = row & (TT - 1);
        const float* kp = g_K + (size_t)t * (NHKV * DHD) + hkv * DHD;
        float v[4], a[4];
#pragma unroll
        for (int q = 0; q < 4; q++) {
            v[q] = kp[q * 32 + lane];
            a[q] = fabsf(v[q]);
            buf[w][q * 32 + lane] = a[q];
        }
        __syncwarp();
        float cand = -1.f;
#pragma unroll
        for (int q = 0; q < 4; q++) {
            int clt = 0, cle = 0;
            for (int j = 0; j < 128; j++) {
                float x = buf[w][j];
                clt += (x < a[q]);
                cle += (x <= a[q]);
            }
            if (clt <= 63 && 63 < cle) cand = a[q];
        }
#pragma unroll
        for (int off = 16; off; off >>= 1)
            cand = fmaxf(cand, __shfl_xor_sync(0xffffffffu, cand, off));

        uint32_t nb[4];
        int ncnt = 0;
#pragma unroll
        for (int q = 0; q < 4; q++) {
            nb[q] = __ballot_sync(0xffffffffu, fabsf(a[q] - cand) < KMARG);
            ncnt += __popc(nb[q]);
        }
        if (ncnt >= 2) {
            const float* hsrow = hs + (size_t)t * HIDD;
#pragma unroll
            for (int q = 0; q < 4; q++) {
                uint32_t bits = nb[q];
                while (bits) {
                    int ln = __ffs(bits) - 1;
                    bits &= bits - 1;
                    int d  = q * 32 + ln;
                    int dd = d & 63;
                    int d2 = (d < 64) ? d + 64 : d - 64;
                    float s1 = coop_dot(hsrow, Wk + (size_t)(hkv * DHD + d)  * HIDD, lane);
                    float s2 = coop_dot(hsrow, Wk + (size_t)(hkv * DHD + d2) * HIDD, lane);
                    float c, s;
                    sincosf((float)t * g_invf[dd], &s, &c);
                    float ex = (d < 64) ? (s1 * c - s2 * s) : (s1 * c + s2 * s);
                    if (lane == ln) {
                        v[q] = ex;
                        a[q] = fabsf(ex);
                        buf[w][d] = a[q];
                    }
                }
            }
            __syncwarp();
            cand = -1.f;
#pragma unroll
            for (int q = 0; q < 4; q++) {
                int clt = 0, cle = 0;
                for (int j = 0; j < 128; j++) {
                    float x = buf[w][j];
                    clt += (x < a[q]);
                    cle += (x <= a[q]);
                }
                if (clt <= 63 && 63 < cle) cand = a[q];
            }
#pragma unroll
            for (int off = 16; off; off >>= 1)
                cand = fmaxf(cand, __shfl_xor_sync(0xffffffffu, cand, off));
        }

        float* op = outK + (size_t)row * DHD;
#pragma unroll
        for (int q = 0; q < 4; q++)
            op[q * 32 + lane] = (a[q] >= cand) ? v[q] : 0.f;
        __syncwarp();
    }
}

// --------- V pruning with fp32 boundary repair ------------------------------
__device__ void prune_v_rows(float* __restrict__ outV, const float* __restrict__ hs,
                             const float* __restrict__ Wv, int gw, int stride, int nloops) {
    const int w = threadIdx.x >> 5, lane = threadIdx.x & 31;
    __shared__ float buf[8][128];
    for (int it = 0; it < nloops; it++) {
        const int row = gw + it * stride;
        const int hkv = row >> 11, t = row & (TT - 1);
        const float* vp = g_V + (size_t)t * (NHKV * DHD) + hkv * DHD;
        float* op = outV + (size_t)row * DHD;
        float v[4];
#pragma unroll
        for (int q = 0; q < 4; q++) v[q] = vp[q * 32 + lane];

        if (t >= TT - GSZ) {
#pragma unroll
            for (int q = 0; q < 4; q++) op[q * 32 + lane] = v[q];
            continue;
        }
        const float rel = g_rel[hkv * TT + t];
        float sc[4];
#pragma unroll
        for (int q = 0; q < 4; q++) {
            sc[q] = fabsf(rel * v[q]);
            buf[w][q * 32 + lane] = sc[q];
        }
        __syncwarp();
        float cand = -1.f;
#pragma unroll
        for (int q = 0; q < 4; q++) {
            int clt = 0, cle = 0;
            for (int j = 0; j < 128; j++) {
                float x = buf[w][j];
                clt += (x < sc[q]);
                cle += (x <= sc[q]);
            }
            if (clt <= 64 && 64 < cle) cand = sc[q];
        }
#pragma unroll
        for (int off = 16; off; off >>= 1)
            cand = fmaxf(cand, __shfl_xor_sync(0xffffffffu, cand, off));

        const float marg = rel * VMARG;
        uint32_t nb[4];
        int ncnt = 0;
#pragma unroll
        for (int q = 0; q < 4; q++) {
            nb[q] = __ballot_sync(0xffffffffu, fabsf(sc[q] - cand) < marg);
            ncnt += __popc(nb[q]);
        }
        if (ncnt >= 2) {
            const float* hsrow = hs + (size_t)t * HIDD;
#pragma unroll
            for (int q = 0; q < 4; q++) {
                uint32_t bits = nb[q];
                while (bits) {
                    int ln = __ffs(bits) - 1;
                    bits &= bits - 1;
                    int d = q * 32 + ln;
                    float ex = coop_dot(hsrow, Wv + (size_t)(hkv * DHD + d) * HIDD, lane);
                    if (lane == ln) {
                        v[q] = ex;
                        sc[q] = fabsf(rel * ex);
                        buf[w][d] = sc[q];
                    }
                }
            }
            __syncwarp();
            cand = -1.f;
#pragma unroll
            for (int q = 0; q < 4; q++) {
                int clt = 0, cle = 0;
                for (int j = 0; j < 128; j++) {
                    float x = buf[w][j];
                    clt += (x < sc[q]);
                    cle += (x <= sc[q]);
                }
                if (clt <= 64 && 64 < cle) cand = sc[q];
            }
#pragma unroll
            for (int off = 16; off; off >>= 1)
                cand = fmaxf(cand, __shfl_xor_sync(0xffffffffu, cand, off));
        }

#pragma unroll
        for (int q = 0; q < 4; q++)
            op[q * 32 + lane] = (sc[q] >= cand) ? v[q] : 0.f;
        __syncwarp();
    }
}

// === fat phase 2: attn 2-head (z=0) + rel (z=1,2) + prune_k (z=3) ==========
__global__ __launch_bounds__(256, 1)
void fat_phase2(float* __restrict__ outK, const float* __restrict__ hs,
                const float* __restrict__ Wk) {
    extern __shared__ char smraw[];
    if (blockIdx.z == 0) {
        attn_body(smraw);
    } else if (blockIdx.z < 3) {
        rel_body((blockIdx.z - 1) * 16 + blockIdx.y);
    } else {
        const int gw = (blockIdx.y * 32 + blockIdx.x) * 8 + (threadIdx.x >> 5);
        prune_k_rows(outK, hs, Wk, gw, 4096, 4);
    }
}

// ======== fat phase 3: Wo bf16x3 HMMA (z=0) + prune_v (z=1) ================
__global__ __launch_bounds__(256, 1)
void fat_phase3(const __nv_bfloat16* __restrict__ cxH, const __nv_bfloat16* __restrict__ cxL,
                const __nv_bfloat16* __restrict__ WoH, const __nv_bfloat16* __restrict__ WoL,
                float* __restrict__ outA, float* __restrict__ outV,
                const float* __restrict__ hs, const float* __restrict__ Wv) {
    extern __shared__ char smraw[];
    if (blockIdx.z == 0) {
        gemm_body(cxH, cxL, WoH, WoL, outA, 4096, 4096, blockIdx.x, blockIdx.y, smraw);
    } else {
        const int gw = (blockIdx.y * 32 + blockIdx.x) * 8 + (threadIdx.x >> 5);
        prune_v_rows(outV, hs, Wv, gw, 4096, 4);
    }
}

// ---------------- launcher -------------------------------------------------
extern "C" void kernel_launch(void* const* d_in, const int* in_sizes, int n_in,
                              void* d_out, int out_size) {
    const float* hs = (const float*)d_in[0];
    const float* Wq = (const float*)d_in[1];
    const float* Wk = (const float*)d_in[2];
    const float* Wv = (const float*)d_in[3];
    const float* Wo = (const float*)d_in[4];

    float* outA = (float*)d_out;
    float* outK = outA + (size_t)TT * HIDD;
    float* outV = outK + (size_t)NHKV * TT * DHD;

    __nv_bfloat16 *hsH, *hsL, *cxH, *cxL, *WqH, *WqL, *WoH, *WoL;
    __nv_bfloat16 *WkH, *WkL, *WvH, *WvL;
    cudaGetSymbolAddress((void**)&hsH, g_hs_hi); cudaGetSymbolAddress((void**)&hsL, g_hs_lo);
    cudaGetSymbolAddress((void**)&cxH, g_cx_hi); cudaGetSymbolAddress((void**)&cxL, g_cx_lo);
    cudaGetSymbolAddress((void**)&WqH, g_Wq_hi); cudaGetSymbolAddress((void**)&WqL, g_Wq_lo);
    cudaGetSymbolAddress((void**)&WoH, g_Wo_hi); cudaGetSymbolAddress((void**)&WoL, g_Wo_lo);
    cudaGetSymbolAddress((void**)&WkH, g_Wk_hi); cudaGetSymbolAddress((void**)&WkL, g_Wk_lo);
    cudaGetSymbolAddress((void**)&WvH, g_Wv_hi); cudaGetSymbolAddress((void**)&WvL, g_Wv_lo);

    cudaFuncSetAttribute(fat_phase1, cudaFuncAttributeMaxDynamicSharedMemorySize, GEMM_SMEM);
    cudaFuncSetAttribute(fat_phase2, cudaFuncAttributeMaxDynamicSharedMemorySize, ATT_SMEM);
    cudaFuncSetAttribute(fat_phase3, cudaFuncAttributeMaxDynamicSharedMemorySize, GEMM_SMEM);

    // fused splits + invfreq init + g_rel zero (one BW-bound launch)
    split_all_kernel<<<SPL_HALF / 256, 256>>>(hs, Wq, Wo, Wk, Wv);

    // Phase 1: all projections on tensor cores (round-15 proven config)
    fat_phase1<<<dim3(32, 8, 3), 256, GEMM_SMEM>>>(hsH, hsL, WqH, WqL, WkH, WkL, WvH, WvL);

    rope_kernel<<<TT, 256>>>();    // RoPE + K/V bf16 split

    // Phase 2: attention + rel + prune_k (fp32 boundary repair)
    fat_phase2<<<dim3(32, 16, 4), 256, ATT_SMEM>>>(outK, hs, Wk);

    // Phase 3: Wo HMMA + prune_v (fp32 boundary repair)
    fat_phase3<<<dim3(32, 16, 2), 256, GEMM_SMEM>>>(cxH, cxL, WoH, WoL, outA, outV, hs, Wv);
}